// round 15
// baseline (speedup 1.0000x reference)
#include <cuda_runtime.h>
#include <cuda_bf16.h>
#include <cstdint>

#define HID 1024
#define NH 16
#define DH 64
#define TT 2048
#define TSEQ 2048
#define BB 4
#define MR (TT*BB)          // 8192 rows for projections
#define ROWSTR (BB*HID)     // 4096 elements per t-step
#define LOG2E 1.4426950408889634f

// ---------------- scratch ----------------
__device__ __nv_bfloat16 g_qh[(size_t)MR * HID];
__device__ __nv_bfloat16 g_kh[(size_t)MR * HID];
__device__ __nv_bfloat16 g_vh[(size_t)MR * HID];
__device__ __nv_bfloat16 g_xq[(size_t)MR * HID];
__device__ __nv_bfloat16 g_xk[(size_t)MR * HID];
__device__ __nv_bfloat16 g_xv[(size_t)MR * HID];
__device__ __nv_bfloat16 g_wq[(size_t)HID * HID];
__device__ __nv_bfloat16 g_wk[(size_t)HID * HID];
__device__ __nv_bfloat16 g_wv[(size_t)HID * HID];

// ---------------- helpers ----------------
__device__ __forceinline__ uint32_t pack_bf16(float lo, float hi) {
    uint32_t d;
    asm("cvt.rn.bf16x2.f32 %0, %1, %2;" : "=r"(d) : "f"(hi), "f"(lo));
    return d;
}
__device__ __forceinline__ float ex2(float x) {
    float r; asm("ex2.approx.f32 %0, %1;" : "=f"(r) : "f"(x)); return r;
}
__device__ __forceinline__ uint32_t ex2b2(uint32_t x) {
    uint32_t r; asm("ex2.approx.ftz.bf16x2 %0, %1;" : "=r"(r) : "r"(x)); return r;
}
__device__ __forceinline__ uint32_t smem_u32(const void* p) {
    return (uint32_t)__cvta_generic_to_shared(p);
}
__device__ __forceinline__ void ldsm_x4(uint32_t& r0, uint32_t& r1,
                                        uint32_t& r2, uint32_t& r3, uint32_t a) {
    asm volatile("ldmatrix.sync.aligned.m8n8.x4.shared.b16 {%0,%1,%2,%3}, [%4];"
                 : "=r"(r0), "=r"(r1), "=r"(r2), "=r"(r3) : "r"(a));
}
__device__ __forceinline__ void ldsm_x4t(uint32_t& r0, uint32_t& r1,
                                         uint32_t& r2, uint32_t& r3, uint32_t a) {
    asm volatile("ldmatrix.sync.aligned.m8n8.x4.trans.shared.b16 {%0,%1,%2,%3}, [%4];"
                 : "=r"(r0), "=r"(r1), "=r"(r2), "=r"(r3) : "r"(a));
}
__device__ __forceinline__ void ldsm_x2t(uint32_t& r0, uint32_t& r1, uint32_t a) {
    asm volatile("ldmatrix.sync.aligned.m8n8.x2.trans.shared.b16 {%0,%1}, [%2];"
                 : "=r"(r0), "=r"(r1) : "r"(a));
}
__device__ __forceinline__ void mma_bf16(float* c, const uint32_t* a, const uint32_t* b) {
    asm volatile(
        "mma.sync.aligned.m16n8k16.row.col.f32.bf16.bf16.f32 "
        "{%0,%1,%2,%3}, {%4,%5,%6,%7}, {%8,%9}, {%0,%1,%2,%3};"
        : "+f"(c[0]), "+f"(c[1]), "+f"(c[2]), "+f"(c[3])
        : "r"(a[0]), "r"(a[1]), "r"(a[2]), "r"(a[3]), "r"(b[0]), "r"(b[1]));
}
__device__ __forceinline__ void cp16(uint32_t dst, const void* src) {
    asm volatile("cp.async.cg.shared.global [%0], [%1], 16;" :: "r"(dst), "l"(src) : "memory");
}
__device__ __forceinline__ void cp_commit() {
    asm volatile("cp.async.commit_group;" ::: "memory");
}
template <int N> __device__ __forceinline__ void cp_wait() {
    asm volatile("cp.async.wait_group %0;" :: "n"(N) : "memory");
}

// =================================================================
// fp32 -> bf16 convert, 3 arrays per launch (y-indexed)
// =================================================================
__global__ __launch_bounds__(256) void cvt3_kernel(
    const float* __restrict__ s0, const float* __restrict__ s1,
    const float* __restrict__ s2, __nv_bfloat16* __restrict__ d0,
    __nv_bfloat16* __restrict__ d1, __nv_bfloat16* __restrict__ d2, int n4)
{
    const float* src = (blockIdx.y == 0) ? s0 : (blockIdx.y == 1) ? s1 : s2;
    __nv_bfloat16* dst = (blockIdx.y == 0) ? d0 : (blockIdx.y == 1) ? d1 : d2;
    int i = blockIdx.x * blockDim.x + threadIdx.x;
    if (i < n4) {
        float4 v = reinterpret_cast<const float4*>(src)[i];
        reinterpret_cast<uint2*>(dst)[i] =
            make_uint2(pack_bf16(v.x, v.y), pack_bf16(v.z, v.w));
    }
}

// =================================================================
// Projection: Y = ReLU6(X @ W^T + bias) * scale, all-bf16 mma.sync
// 128x128 tile, BK=64, 256 threads, 2-stage cp.async, 2 CTAs/SM.
// =================================================================
#define PJS 72
#define PJ_TILE (128 * PJS)
#define PJ_STAGE (2 * PJ_TILE)
#define PJ_STAGE_BYTES (PJ_STAGE * 2)
#define PJ_SMEM (2 * PJ_STAGE_BYTES)

__global__ __launch_bounds__(256, 2) void proj_kernel(
    const __nv_bfloat16* __restrict__ Xq, const __nv_bfloat16* __restrict__ Wq,
    const float* __restrict__ bq, __nv_bfloat16* __restrict__ Yq,
    const __nv_bfloat16* __restrict__ Xk, const __nv_bfloat16* __restrict__ Wk,
    const float* __restrict__ bk, __nv_bfloat16* __restrict__ Yk,
    const __nv_bfloat16* __restrict__ Xv, const __nv_bfloat16* __restrict__ Wv,
    const float* __restrict__ bv, __nv_bfloat16* __restrict__ Yv,
    float sq)
{
    extern __shared__ __align__(16) uint16_t psm[];

    const int tid = threadIdx.x;
    const int lane = tid & 31;
    const int wid = tid >> 5;
    const int g = lane >> 2;
    const int t = lane & 3;
    const int wm = (wid >> 2) * 64;
    const int wn = (wid & 3) * 32;
    const int z = blockIdx.z;
    const int m0 = blockIdx.y * 128;
    const int n0 = blockIdx.x * 128;

    const __nv_bfloat16* X = (z == 0) ? Xq : (z == 1) ? Xk : Xv;
    const __nv_bfloat16* W = (z == 0) ? Wq : (z == 1) ? Wk : Wv;
    const float*      bias = (z == 0) ? bq : (z == 1) ? bk : bv;
    __nv_bfloat16*       Y = (z == 0) ? Yq : (z == 1) ? Yk : Yv;
    const float      scale = (z == 0) ? sq : 1.0f;

    float acc[4][4][4];
#pragma unroll
    for (int mt = 0; mt < 4; mt++)
#pragma unroll
        for (int nt = 0; nt < 4; nt++)
#pragma unroll
            for (int j = 0; j < 4; j++) acc[mt][nt][j] = 0.f;

    const uint32_t smbase = smem_u32(psm);
    const uint32_t abase =
        smbase + ((wm + (lane & 15)) * PJS + (lane >> 4) * 8) * 2;
    const uint32_t bbase =
        smbase + PJ_TILE * 2 +
        ((wn + (lane & 7) + (lane >> 4) * 8) * PJS + ((lane >> 3) & 1) * 8) * 2;

    auto fill = [&](int s, int k0) {
        uint16_t* As = psm + s * PJ_STAGE;
        uint16_t* Bs = As + PJ_TILE;
#pragma unroll
        for (int i = 0; i < 4; i++) {
            int f = tid + i * 256;
            int row = f >> 3;
            int dc = (f & 7) * 8;
            cp16(smem_u32(&As[row * PJS + dc]),
                 X + (size_t)(m0 + row) * HID + k0 + dc);
            cp16(smem_u32(&Bs[row * PJS + dc]),
                 W + (size_t)(n0 + row) * HID + k0 + dc);
        }
        cp_commit();
    };

    fill(0, 0);

    for (int it = 0; it < 16; it++) {
        cp_wait<0>();
        __syncthreads();
        if (it < 15) fill((it + 1) & 1, (it + 1) * 64);

        const uint32_t so = (uint32_t)(it & 1) * PJ_STAGE_BYTES;
        const uint32_t ab = abase + so;
        const uint32_t bb = bbase + so;
#pragma unroll
        for (int kt = 0; kt < 4; kt++) {
            uint32_t af[4][4], bf[4][2];
#pragma unroll
            for (int mt = 0; mt < 4; mt++)
                ldsm_x4(af[mt][0], af[mt][1], af[mt][2], af[mt][3],
                        ab + (mt * 16 * PJS + kt * 16) * 2);
#pragma unroll
            for (int ntp = 0; ntp < 2; ntp++) {
                uint32_t r0, r1, r2, r3;
                ldsm_x4(r0, r1, r2, r3,
                        bb + (ntp * 16 * PJS + kt * 16) * 2);
                bf[2 * ntp][0] = r0; bf[2 * ntp][1] = r1;
                bf[2 * ntp + 1][0] = r2; bf[2 * ntp + 1][1] = r3;
            }
#pragma unroll
            for (int mt = 0; mt < 4; mt++)
#pragma unroll
                for (int nt = 0; nt < 4; nt++)
                    mma_bf16(acc[mt][nt], af[mt], bf[nt]);
        }
    }

#pragma unroll
    for (int nt = 0; nt < 4; nt++) {
        int col = n0 + wn + nt * 8 + 2 * t;
        float b0 = bias[col], b1 = bias[col + 1];
#pragma unroll
        for (int mt = 0; mt < 4; mt++) {
            int r0 = m0 + wm + mt * 16 + g;
            float o0 = fminf(fmaxf(acc[mt][nt][0] + b0, 0.f), 6.f) * scale;
            float o1 = fminf(fmaxf(acc[mt][nt][1] + b1, 0.f), 6.f) * scale;
            float o2 = fminf(fmaxf(acc[mt][nt][2] + b0, 0.f), 6.f) * scale;
            float o3 = fminf(fmaxf(acc[mt][nt][3] + b1, 0.f), 6.f) * scale;
            *reinterpret_cast<uint32_t*>(Y + (size_t)r0 * HID + col) = pack_bf16(o0, o1);
            *reinterpret_cast<uint32_t*>(Y + (size_t)(r0 + 8) * HID + col) = pack_bf16(o2, o3);
        }
    }
}

// =================================================================
// Flash attention, bf16 MMA, 4 warps x 32 Q rows. IDENTICAL code to
// the verified 194us config, but __launch_bounds__(128, 3): forces
// ptxas to <=170 regs so 3 CTAs/SM co-reside (12 warps/SM) to hide
// the per-warp softmax dependency bubble.
// =================================================================
#define AKS 72
#define QS_OFF 0
#define KB_OFF (128 * AKS * 2)
#define VB_OFF (KB_OFF + 2 * 64 * AKS * 2)
#define KVBYTES (64 * AKS * 2)
#define ATT_SMEM (VB_OFF + 2 * 64 * AKS * 2)   // 55296
#define ATH 128

__global__ __launch_bounds__(ATH, 3) void attn_kernel(
    const __nv_bfloat16* __restrict__ qh, const __nv_bfloat16* __restrict__ kh,
    const __nv_bfloat16* __restrict__ vh, float* __restrict__ out)
{
    extern __shared__ __align__(16) char sm[];
    uint16_t* QS = reinterpret_cast<uint16_t*>(sm + QS_OFF);
    uint16_t* KB = reinterpret_cast<uint16_t*>(sm + KB_OFF);
    uint16_t* VB = reinterpret_cast<uint16_t*>(sm + VB_OFF);

    const int tid = threadIdx.x;
    const int lane = tid & 31;
    const int wid = tid >> 5;          // 0..3
    const int g = lane >> 2;
    const int t = lane & 3;
    const int b = blockIdx.z, h = blockIdx.y;
    const int q0 = blockIdx.x * 128;
    const size_t hoff = (size_t)b * HID + (size_t)h * DH;
    const int wrow = wid * 32;         // 32 Q rows per warp

    // ---- stage Q + K/V tile 0 ----
#pragma unroll
    for (int i = 0; i < 8; i++) {
        int f = tid + i * ATH;
        int row = f >> 3;
        int dc = (f & 7) * 8;
        cp16(smem_u32(&QS[row * AKS + dc]),
             qh + (size_t)(q0 + row) * ROWSTR + hoff + dc);
    }
#pragma unroll
    for (int i = 0; i < 4; i++) {
        int f = tid + i * ATH;
        int row = f >> 3;
        int dc = (f & 7) * 8;
        cp16(smem_u32(&KB[row * AKS + dc]), kh + (size_t)row * ROWSTR + hoff + dc);
        cp16(smem_u32(&VB[row * AKS + dc]), vh + (size_t)row * ROWSTR + hoff + dc);
    }
    cp_commit();

    // V padding cols: col 64 = 1.0 bf16, 65..71 = 0, both buffers
    for (int i = tid; i < 2 * 64 * 8; i += ATH) {
        int bufrow = i >> 3;
        int c = i & 7;
        VB[bufrow * AKS + 64 + c] = (c == 0) ? (uint16_t)0x3F80 : (uint16_t)0;
    }

    // hoisted per-lane ldmatrix bases
    const uint32_t kbase =
        smem_u32(KB) + (((lane & 7) + (lane >> 4) * 8) * AKS + ((lane >> 3) & 1) * 8) * 2;
    const uint32_t vbase =
        smem_u32(VB) + (((lane & 7) + ((lane >> 3) & 1) * 8) * AKS + (lane >> 4) * 8) * 2;
    const uint32_t vobase =
        smem_u32(VB) + (((lane & 7) + ((lane >> 3) & 1) * 8) * AKS + 64) * 2;

    cp_wait<0>();
    __syncthreads();

    // ---- persistent Q fragments: 2 m-halves x 4 k-steps ----
    uint32_t qa[2][4][4];
#pragma unroll
    for (int mh = 0; mh < 2; mh++)
#pragma unroll
        for (int kt = 0; kt < 4; kt++)
            ldsm_x4(qa[mh][kt][0], qa[mh][kt][1], qa[mh][kt][2], qa[mh][kt][3],
                    smem_u32(&QS[(wrow + mh * 16 + (lane & 15)) * AKS +
                                 kt * 16 + (lane >> 4) * 8]));

    float O[2][8][4], Oex[2][4];
#pragma unroll
    for (int mh = 0; mh < 2; mh++) {
#pragma unroll
        for (int nt = 0; nt < 8; nt++)
#pragma unroll
            for (int j = 0; j < 4; j++) O[mh][nt][j] = 0.f;
#pragma unroll
        for (int j = 0; j < 4; j++) Oex[mh][j] = 0.f;
    }
    float mrun[2][2];
    mrun[0][0] = mrun[0][1] = mrun[1][0] = mrun[1][1] = -1e30f;

    for (int it = 0; it < TSEQ / 64; it++) {
        const uint32_t bo = (uint32_t)(it & 1) * KVBYTES;

        if (it > 0) {
            cp_wait<0>();
            __syncthreads();
        }
        if (it < TSEQ / 64 - 1) {
            int s0n = (it + 1) * 64;
            uint16_t* Kn = KB + ((it + 1) & 1) * 64 * AKS;
            uint16_t* Vn = VB + ((it + 1) & 1) * 64 * AKS;
#pragma unroll
            for (int i = 0; i < 4; i++) {
                int f = tid + i * ATH;
                int row = f >> 3;
                int dc = (f & 7) * 8;
                cp16(smem_u32(&Kn[row * AKS + dc]),
                     kh + (size_t)(s0n + row) * ROWSTR + hoff + dc);
                cp16(smem_u32(&Vn[row * AKS + dc]),
                     vh + (size_t)(s0n + row) * ROWSTR + hoff + dc);
            }
            cp_commit();
        }

        // ---- S = Q K^T, both m-halves share each K fragment ----
        float sacc[2][8][4];
#pragma unroll
        for (int mh = 0; mh < 2; mh++)
#pragma unroll
            for (int nt = 0; nt < 8; nt++)
#pragma unroll
                for (int j = 0; j < 4; j++) sacc[mh][nt][j] = 0.f;
        const uint32_t kb = kbase + bo;
#pragma unroll
        for (int ntp = 0; ntp < 4; ntp++) {
#pragma unroll
            for (int kt = 0; kt < 4; kt++) {
                uint32_t r0, r1, r2, r3;
                ldsm_x4(r0, r1, r2, r3, kb + (ntp * 16 * AKS + kt * 16) * 2);
                uint32_t blo[2] = {r0, r1}, bhi[2] = {r2, r3};
#pragma unroll
                for (int mh = 0; mh < 2; mh++) {
                    mma_bf16(sacc[mh][2 * ntp], qa[mh][kt], blo);
                    mma_bf16(sacc[mh][2 * ntp + 1], qa[mh][kt], bhi);
                }
            }
        }

        // ---- online softmax per m-half ----
        float mn[2][2], fs[2][2];
        bool upd = false;
#pragma unroll
        for (int mh = 0; mh < 2; mh++) {
            float mx0 = -1e30f, mx1 = -1e30f;
#pragma unroll
            for (int nt = 0; nt < 8; nt++) {
                mx0 = fmaxf(mx0, fmaxf(sacc[mh][nt][0], sacc[mh][nt][1]));
                mx1 = fmaxf(mx1, fmaxf(sacc[mh][nt][2], sacc[mh][nt][3]));
            }
            mx0 = fmaxf(mx0, __shfl_xor_sync(0xffffffff, mx0, 1));
            mx0 = fmaxf(mx0, __shfl_xor_sync(0xffffffff, mx0, 2));
            mx1 = fmaxf(mx1, __shfl_xor_sync(0xffffffff, mx1, 1));
            mx1 = fmaxf(mx1, __shfl_xor_sync(0xffffffff, mx1, 2));
            mn[mh][0] = fmaxf(mrun[mh][0], mx0);
            mn[mh][1] = fmaxf(mrun[mh][1], mx1);
            upd |= (mn[mh][0] > mrun[mh][0]) || (mn[mh][1] > mrun[mh][1]);
        }
        if (__any_sync(0xffffffffu, upd)) {
#pragma unroll
            for (int mh = 0; mh < 2; mh++) {
                fs[mh][0] = ex2(mrun[mh][0] - mn[mh][0]);
                fs[mh][1] = ex2(mrun[mh][1] - mn[mh][1]);
                mrun[mh][0] = mn[mh][0]; mrun[mh][1] = mn[mh][1];
#pragma unroll
                for (int nt = 0; nt < 8; nt++) {
                    O[mh][nt][0] *= fs[mh][0]; O[mh][nt][1] *= fs[mh][0];
                    O[mh][nt][2] *= fs[mh][1]; O[mh][nt][3] *= fs[mh][1];
                }
                Oex[mh][0] *= fs[mh][0]; Oex[mh][1] *= fs[mh][0];
                Oex[mh][2] *= fs[mh][1]; Oex[mh][3] *= fs[mh][1];
            }
        }

        uint32_t pa[2][4][4];
#pragma unroll
        for (int mh = 0; mh < 2; mh++)
#pragma unroll
            for (int nt = 0; nt < 8; nt++) {
                uint32_t dlo = pack_bf16(sacc[mh][nt][0] - mn[mh][0],
                                         sacc[mh][nt][1] - mn[mh][0]);
                uint32_t dhi = pack_bf16(sacc[mh][nt][2] - mn[mh][1],
                                         sacc[mh][nt][3] - mn[mh][1]);
                uint32_t p01 = ex2b2(dlo);
                uint32_t p23 = ex2b2(dhi);
                int kt = nt >> 1;
                if ((nt & 1) == 0) { pa[mh][kt][0] = p01; pa[mh][kt][1] = p23; }
                else               { pa[mh][kt][2] = p01; pa[mh][kt][3] = p23; }
            }

        // ---- O += P V, both m-halves share each V fragment ----
        const uint32_t vb = vbase + bo;
        const uint32_t vo = vobase + bo;
#pragma unroll
        for (int ntp = 0; ntp < 4; ntp++) {
#pragma unroll
            for (int kt = 0; kt < 4; kt++) {
                uint32_t r0, r1, r2, r3;
                ldsm_x4t(r0, r1, r2, r3, vb + (kt * 16 * AKS + ntp * 16) * 2);
                uint32_t blo[2] = {r0, r1}, bhi[2] = {r2, r3};
#pragma unroll
                for (int mh = 0; mh < 2; mh++) {
                    mma_bf16(O[mh][2 * ntp], pa[mh][kt], blo);
                    mma_bf16(O[mh][2 * ntp + 1], pa[mh][kt], bhi);
                }
            }
        }
#pragma unroll
        for (int kt = 0; kt < 4; kt++) {
            uint32_t r0, r1;
            ldsm_x2t(r0, r1, vo + (kt * 16 * AKS) * 2);
            uint32_t bx[2] = {r0, r1};
#pragma unroll
            for (int mh = 0; mh < 2; mh++)
                mma_bf16(Oex[mh], pa[mh][kt], bx);
        }
    }

    // ---- epilogue: row sums from quad leader, normalize, store ----
    const int qlead = lane & ~3;
#pragma unroll
    for (int mh = 0; mh < 2; mh++) {
        float l0 = __shfl_sync(0xffffffff, Oex[mh][0], qlead);
        float l1 = __shfl_sync(0xffffffff, Oex[mh][2], qlead);
        float il0 = 1.f / l0, il1 = 1.f / l1;
        const int gr0 = q0 + wrow + mh * 16 + g, gr1 = gr0 + 8;
#pragma unroll
        for (int nt = 0; nt < 8; nt++) {
            int col = nt * 8 + 2 * t;
            float2 o0 = {O[mh][nt][0] * il0, O[mh][nt][1] * il0};
            float2 o1 = {O[mh][nt][2] * il1, O[mh][nt][3] * il1};
            *reinterpret_cast<float2*>(out + (size_t)gr0 * ROWSTR + hoff + col) = o0;
            *reinterpret_cast<float2*>(out + (size_t)gr1 * ROWSTR + hoff + col) = o1;
        }
    }
}

// =================================================================
extern "C" void kernel_launch(void* const* d_in, const int* in_sizes, int n_in,
                              void* d_out, int out_size)
{
    const float* q  = (const float*)d_in[0];
    const float* k  = (const float*)d_in[1];
    const float* v  = (const float*)d_in[2];
    const float* Wq = (const float*)d_in[3];
    const float* bq = (const float*)d_in[4];
    const float* Wk = (const float*)d_in[5];
    const float* bk = (const float*)d_in[6];
    const float* Wv = (const float*)d_in[7];
    const float* bv = (const float*)d_in[8];
    float* out = (float*)d_out;

    __nv_bfloat16 *qh, *kh, *vh, *xq, *xk, *xv, *wq, *wk, *wv;
    cudaGetSymbolAddress((void**)&qh, g_qh);
    cudaGetSymbolAddress((void**)&kh, g_kh);
    cudaGetSymbolAddress((void**)&vh, g_vh);
    cudaGetSymbolAddress((void**)&xq, g_xq);
    cudaGetSymbolAddress((void**)&xk, g_xk);
    cudaGetSymbolAddress((void**)&xv, g_xv);
    cudaGetSymbolAddress((void**)&wq, g_wq);
    cudaGetSymbolAddress((void**)&wk, g_wk);
    cudaGetSymbolAddress((void**)&wv, g_wv);

    const int n4i = MR * HID / 4;
    const int n4w = HID * HID / 4;
    cvt3_kernel<<<dim3(n4i / 256, 3), 256>>>(q, k, v, xq, xk, xv, n4i);
    cvt3_kernel<<<dim3(n4w / 256, 3), 256>>>(Wq, Wk, Wv, wq, wk, wv, n4w);

    cudaFuncSetAttribute(proj_kernel,
                         cudaFuncAttributeMaxDynamicSharedMemorySize, PJ_SMEM);
    dim3 pg(HID / 128, MR / 128, 3);
    proj_kernel<<<pg, 256, PJ_SMEM>>>(
        xq, wq, bq, qh,
        xk, wk, bk, kh,
        xv, wv, bv, vh,
        0.125f * LOG2E);

    cudaFuncSetAttribute(attn_kernel,
                         cudaFuncAttributeMaxDynamicSharedMemorySize, ATT_SMEM);
    dim3 ag(TT / 128, NH, BB);
    attn_kernel<<<ag, ATH, ATT_SMEM>>>(qh, kh, vh, out);
}

// round 16
// speedup vs baseline: 1.1592x; 1.1592x over previous
#include <cuda_runtime.h>
#include <cuda_bf16.h>
#include <cstdint>

#define HID 1024
#define NH 16
#define DH 64
#define TT 2048
#define TSEQ 2048
#define BB 4
#define MR (TT*BB)          // 8192 rows for projections
#define ROWSTR (BB*HID)     // 4096 elements per t-step
#define LOG2E 1.4426950408889634f

// ---------------- scratch ----------------
__device__ __nv_bfloat16 g_qh[(size_t)MR * HID];
__device__ __nv_bfloat16 g_kh[(size_t)MR * HID];
__device__ __nv_bfloat16 g_vh[(size_t)MR * HID];
__device__ __nv_bfloat16 g_xq[(size_t)MR * HID];
__device__ __nv_bfloat16 g_xk[(size_t)MR * HID];
__device__ __nv_bfloat16 g_xv[(size_t)MR * HID];
__device__ __nv_bfloat16 g_wq[(size_t)HID * HID];
__device__ __nv_bfloat16 g_wk[(size_t)HID * HID];
__device__ __nv_bfloat16 g_wv[(size_t)HID * HID];

// ---------------- helpers ----------------
__device__ __forceinline__ uint32_t pack_bf16(float lo, float hi) {
    uint32_t d;
    asm("cvt.rn.bf16x2.f32 %0, %1, %2;" : "=r"(d) : "f"(hi), "f"(lo));
    return d;
}
__device__ __forceinline__ float ex2(float x) {
    float r; asm("ex2.approx.f32 %0, %1;" : "=f"(r) : "f"(x)); return r;
}
__device__ __forceinline__ uint32_t ex2b2(uint32_t x) {
    uint32_t r; asm("ex2.approx.ftz.bf16x2 %0, %1;" : "=r"(r) : "r"(x)); return r;
}
__device__ __forceinline__ uint32_t smem_u32(const void* p) {
    return (uint32_t)__cvta_generic_to_shared(p);
}
__device__ __forceinline__ void ldsm_x4(uint32_t& r0, uint32_t& r1,
                                        uint32_t& r2, uint32_t& r3, uint32_t a) {
    asm volatile("ldmatrix.sync.aligned.m8n8.x4.shared.b16 {%0,%1,%2,%3}, [%4];"
                 : "=r"(r0), "=r"(r1), "=r"(r2), "=r"(r3) : "r"(a));
}
__device__ __forceinline__ void ldsm_x4t(uint32_t& r0, uint32_t& r1,
                                         uint32_t& r2, uint32_t& r3, uint32_t a) {
    asm volatile("ldmatrix.sync.aligned.m8n8.x4.trans.shared.b16 {%0,%1,%2,%3}, [%4];"
                 : "=r"(r0), "=r"(r1), "=r"(r2), "=r"(r3) : "r"(a));
}
__device__ __forceinline__ void ldsm_x2t(uint32_t& r0, uint32_t& r1, uint32_t a) {
    asm volatile("ldmatrix.sync.aligned.m8n8.x2.trans.shared.b16 {%0,%1}, [%2];"
                 : "=r"(r0), "=r"(r1) : "r"(a));
}
__device__ __forceinline__ void mma_bf16(float* c, const uint32_t* a, const uint32_t* b) {
    asm volatile(
        "mma.sync.aligned.m16n8k16.row.col.f32.bf16.bf16.f32 "
        "{%0,%1,%2,%3}, {%4,%5,%6,%7}, {%8,%9}, {%0,%1,%2,%3};"
        : "+f"(c[0]), "+f"(c[1]), "+f"(c[2]), "+f"(c[3])
        : "r"(a[0]), "r"(a[1]), "r"(a[2]), "r"(a[3]), "r"(b[0]), "r"(b[1]));
}
__device__ __forceinline__ void cp16(uint32_t dst, const void* src) {
    asm volatile("cp.async.cg.shared.global [%0], [%1], 16;" :: "r"(dst), "l"(src) : "memory");
}
__device__ __forceinline__ void cp_commit() {
    asm volatile("cp.async.commit_group;" ::: "memory");
}
template <int N> __device__ __forceinline__ void cp_wait() {
    asm volatile("cp.async.wait_group %0;" :: "n"(N) : "memory");
}

// =================================================================
// fp32 -> bf16 convert, 3 arrays per launch (y-indexed)
// =================================================================
__global__ __launch_bounds__(256) void cvt3_kernel(
    const float* __restrict__ s0, const float* __restrict__ s1,
    const float* __restrict__ s2, __nv_bfloat16* __restrict__ d0,
    __nv_bfloat16* __restrict__ d1, __nv_bfloat16* __restrict__ d2, int n4)
{
    const float* src = (blockIdx.y == 0) ? s0 : (blockIdx.y == 1) ? s1 : s2;
    __nv_bfloat16* dst = (blockIdx.y == 0) ? d0 : (blockIdx.y == 1) ? d1 : d2;
    int i = blockIdx.x * blockDim.x + threadIdx.x;
    if (i < n4) {
        float4 v = reinterpret_cast<const float4*>(src)[i];
        reinterpret_cast<uint2*>(dst)[i] =
            make_uint2(pack_bf16(v.x, v.y), pack_bf16(v.z, v.w));
    }
}

// =================================================================
// Projection: Y = ReLU6(X @ W^T + bias) * scale, all-bf16 mma.sync
// 128x128 tile, BK=64, 256 threads, 2-stage cp.async, 2 CTAs/SM.
// =================================================================
#define PJS 72
#define PJ_TILE (128 * PJS)
#define PJ_STAGE (2 * PJ_TILE)
#define PJ_STAGE_BYTES (PJ_STAGE * 2)
#define PJ_SMEM (2 * PJ_STAGE_BYTES)

__global__ __launch_bounds__(256, 2) void proj_kernel(
    const __nv_bfloat16* __restrict__ Xq, const __nv_bfloat16* __restrict__ Wq,
    const float* __restrict__ bq, __nv_bfloat16* __restrict__ Yq,
    const __nv_bfloat16* __restrict__ Xk, const __nv_bfloat16* __restrict__ Wk,
    const float* __restrict__ bk, __nv_bfloat16* __restrict__ Yk,
    const __nv_bfloat16* __restrict__ Xv, const __nv_bfloat16* __restrict__ Wv,
    const float* __restrict__ bv, __nv_bfloat16* __restrict__ Yv,
    float sq)
{
    extern __shared__ __align__(16) uint16_t psm[];

    const int tid = threadIdx.x;
    const int lane = tid & 31;
    const int wid = tid >> 5;
    const int g = lane >> 2;
    const int t = lane & 3;
    const int wm = (wid >> 2) * 64;
    const int wn = (wid & 3) * 32;
    const int z = blockIdx.z;
    const int m0 = blockIdx.y * 128;
    const int n0 = blockIdx.x * 128;

    const __nv_bfloat16* X = (z == 0) ? Xq : (z == 1) ? Xk : Xv;
    const __nv_bfloat16* W = (z == 0) ? Wq : (z == 1) ? Wk : Wv;
    const float*      bias = (z == 0) ? bq : (z == 1) ? bk : bv;
    __nv_bfloat16*       Y = (z == 0) ? Yq : (z == 1) ? Yk : Yv;
    const float      scale = (z == 0) ? sq : 1.0f;

    float acc[4][4][4];
#pragma unroll
    for (int mt = 0; mt < 4; mt++)
#pragma unroll
        for (int nt = 0; nt < 4; nt++)
#pragma unroll
            for (int j = 0; j < 4; j++) acc[mt][nt][j] = 0.f;

    const uint32_t smbase = smem_u32(psm);
    const uint32_t abase =
        smbase + ((wm + (lane & 15)) * PJS + (lane >> 4) * 8) * 2;
    const uint32_t bbase =
        smbase + PJ_TILE * 2 +
        ((wn + (lane & 7) + (lane >> 4) * 8) * PJS + ((lane >> 3) & 1) * 8) * 2;

    auto fill = [&](int s, int k0) {
        uint16_t* As = psm + s * PJ_STAGE;
        uint16_t* Bs = As + PJ_TILE;
#pragma unroll
        for (int i = 0; i < 4; i++) {
            int f = tid + i * 256;
            int row = f >> 3;
            int dc = (f & 7) * 8;
            cp16(smem_u32(&As[row * PJS + dc]),
                 X + (size_t)(m0 + row) * HID + k0 + dc);
            cp16(smem_u32(&Bs[row * PJS + dc]),
                 W + (size_t)(n0 + row) * HID + k0 + dc);
        }
        cp_commit();
    };

    fill(0, 0);

    for (int it = 0; it < 16; it++) {
        cp_wait<0>();
        __syncthreads();
        if (it < 15) fill((it + 1) & 1, (it + 1) * 64);

        const uint32_t so = (uint32_t)(it & 1) * PJ_STAGE_BYTES;
        const uint32_t ab = abase + so;
        const uint32_t bb = bbase + so;
#pragma unroll
        for (int kt = 0; kt < 4; kt++) {
            uint32_t af[4][4], bf[4][2];
#pragma unroll
            for (int mt = 0; mt < 4; mt++)
                ldsm_x4(af[mt][0], af[mt][1], af[mt][2], af[mt][3],
                        ab + (mt * 16 * PJS + kt * 16) * 2);
#pragma unroll
            for (int ntp = 0; ntp < 2; ntp++) {
                uint32_t r0, r1, r2, r3;
                ldsm_x4(r0, r1, r2, r3,
                        bb + (ntp * 16 * PJS + kt * 16) * 2);
                bf[2 * ntp][0] = r0; bf[2 * ntp][1] = r1;
                bf[2 * ntp + 1][0] = r2; bf[2 * ntp + 1][1] = r3;
            }
#pragma unroll
            for (int mt = 0; mt < 4; mt++)
#pragma unroll
                for (int nt = 0; nt < 4; nt++)
                    mma_bf16(acc[mt][nt], af[mt], bf[nt]);
        }
    }

#pragma unroll
    for (int nt = 0; nt < 4; nt++) {
        int col = n0 + wn + nt * 8 + 2 * t;
        float b0 = bias[col], b1 = bias[col + 1];
#pragma unroll
        for (int mt = 0; mt < 4; mt++) {
            int r0 = m0 + wm + mt * 16 + g;
            float o0 = fminf(fmaxf(acc[mt][nt][0] + b0, 0.f), 6.f) * scale;
            float o1 = fminf(fmaxf(acc[mt][nt][1] + b1, 0.f), 6.f) * scale;
            float o2 = fminf(fmaxf(acc[mt][nt][2] + b0, 0.f), 6.f) * scale;
            float o3 = fminf(fmaxf(acc[mt][nt][3] + b1, 0.f), 6.f) * scale;
            *reinterpret_cast<uint32_t*>(Y + (size_t)r0 * HID + col) = pack_bf16(o0, o1);
            *reinterpret_cast<uint32_t*>(Y + (size_t)(r0 + 8) * HID + col) = pack_bf16(o2, o3);
        }
    }
}

// =================================================================
// Flash attention, bf16 MMA, 4 warps x 32 Q rows: each K/V ldmatrix
// feeds TWO m16 MMAs. bf16x2 ex2 softmax, ones-column row sums,
// vote-skip rescale, double-buffered K/V. (Verified 194us config.)
// =================================================================
#define AKS 72
#define QS_OFF 0
#define KB_OFF (128 * AKS * 2)
#define VB_OFF (KB_OFF + 2 * 64 * AKS * 2)
#define KVBYTES (64 * AKS * 2)
#define ATT_SMEM (VB_OFF + 2 * 64 * AKS * 2)   // 55296
#define ATH 128

__global__ __launch_bounds__(ATH, 2) void attn_kernel(
    const __nv_bfloat16* __restrict__ qh, const __nv_bfloat16* __restrict__ kh,
    const __nv_bfloat16* __restrict__ vh, float* __restrict__ out)
{
    extern __shared__ __align__(16) char sm[];
    uint16_t* QS = reinterpret_cast<uint16_t*>(sm + QS_OFF);
    uint16_t* KB = reinterpret_cast<uint16_t*>(sm + KB_OFF);
    uint16_t* VB = reinterpret_cast<uint16_t*>(sm + VB_OFF);

    const int tid = threadIdx.x;
    const int lane = tid & 31;
    const int wid = tid >> 5;          // 0..3
    const int g = lane >> 2;
    const int t = lane & 3;
    const int b = blockIdx.z, h = blockIdx.y;
    const int q0 = blockIdx.x * 128;
    const size_t hoff = (size_t)b * HID + (size_t)h * DH;
    const int wrow = wid * 32;         // 32 Q rows per warp

    // ---- stage Q + K/V tile 0 ----
#pragma unroll
    for (int i = 0; i < 8; i++) {
        int f = tid + i * ATH;
        int row = f >> 3;
        int dc = (f & 7) * 8;
        cp16(smem_u32(&QS[row * AKS + dc]),
             qh + (size_t)(q0 + row) * ROWSTR + hoff + dc);
    }
#pragma unroll
    for (int i = 0; i < 4; i++) {
        int f = tid + i * ATH;
        int row = f >> 3;
        int dc = (f & 7) * 8;
        cp16(smem_u32(&KB[row * AKS + dc]), kh + (size_t)row * ROWSTR + hoff + dc);
        cp16(smem_u32(&VB[row * AKS + dc]), vh + (size_t)row * ROWSTR + hoff + dc);
    }
    cp_commit();

    // V padding cols: col 64 = 1.0 bf16, 65..71 = 0, both buffers
    for (int i = tid; i < 2 * 64 * 8; i += ATH) {
        int bufrow = i >> 3;
        int c = i & 7;
        VB[bufrow * AKS + 64 + c] = (c == 0) ? (uint16_t)0x3F80 : (uint16_t)0;
    }

    // hoisted per-lane ldmatrix bases
    const uint32_t kbase =
        smem_u32(KB) + (((lane & 7) + (lane >> 4) * 8) * AKS + ((lane >> 3) & 1) * 8) * 2;
    const uint32_t vbase =
        smem_u32(VB) + (((lane & 7) + ((lane >> 3) & 1) * 8) * AKS + (lane >> 4) * 8) * 2;
    const uint32_t vobase =
        smem_u32(VB) + (((lane & 7) + ((lane >> 3) & 1) * 8) * AKS + 64) * 2;

    cp_wait<0>();
    __syncthreads();

    // ---- persistent Q fragments: 2 m-halves x 4 k-steps ----
    uint32_t qa[2][4][4];
#pragma unroll
    for (int mh = 0; mh < 2; mh++)
#pragma unroll
        for (int kt = 0; kt < 4; kt++)
            ldsm_x4(qa[mh][kt][0], qa[mh][kt][1], qa[mh][kt][2], qa[mh][kt][3],
                    smem_u32(&QS[(wrow + mh * 16 + (lane & 15)) * AKS +
                                 kt * 16 + (lane >> 4) * 8]));

    float O[2][8][4], Oex[2][4];
#pragma unroll
    for (int mh = 0; mh < 2; mh++) {
#pragma unroll
        for (int nt = 0; nt < 8; nt++)
#pragma unroll
            for (int j = 0; j < 4; j++) O[mh][nt][j] = 0.f;
#pragma unroll
        for (int j = 0; j < 4; j++) Oex[mh][j] = 0.f;
    }
    float mrun[2][2];
    mrun[0][0] = mrun[0][1] = mrun[1][0] = mrun[1][1] = -1e30f;

    for (int it = 0; it < TSEQ / 64; it++) {
        const uint32_t bo = (uint32_t)(it & 1) * KVBYTES;

        if (it > 0) {
            cp_wait<0>();
            __syncthreads();
        }
        if (it < TSEQ / 64 - 1) {
            int s0n = (it + 1) * 64;
            uint16_t* Kn = KB + ((it + 1) & 1) * 64 * AKS;
            uint16_t* Vn = VB + ((it + 1) & 1) * 64 * AKS;
#pragma unroll
            for (int i = 0; i < 4; i++) {
                int f = tid + i * ATH;
                int row = f >> 3;
                int dc = (f & 7) * 8;
                cp16(smem_u32(&Kn[row * AKS + dc]),
                     kh + (size_t)(s0n + row) * ROWSTR + hoff + dc);
                cp16(smem_u32(&Vn[row * AKS + dc]),
                     vh + (size_t)(s0n + row) * ROWSTR + hoff + dc);
            }
            cp_commit();
        }

        // ---- S = Q K^T, both m-halves share each K fragment ----
        float sacc[2][8][4];
#pragma unroll
        for (int mh = 0; mh < 2; mh++)
#pragma unroll
            for (int nt = 0; nt < 8; nt++)
#pragma unroll
                for (int j = 0; j < 4; j++) sacc[mh][nt][j] = 0.f;
        const uint32_t kb = kbase + bo;
#pragma unroll
        for (int ntp = 0; ntp < 4; ntp++) {
#pragma unroll
            for (int kt = 0; kt < 4; kt++) {
                uint32_t r0, r1, r2, r3;
                ldsm_x4(r0, r1, r2, r3, kb + (ntp * 16 * AKS + kt * 16) * 2);
                uint32_t blo[2] = {r0, r1}, bhi[2] = {r2, r3};
#pragma unroll
                for (int mh = 0; mh < 2; mh++) {
                    mma_bf16(sacc[mh][2 * ntp], qa[mh][kt], blo);
                    mma_bf16(sacc[mh][2 * ntp + 1], qa[mh][kt], bhi);
                }
            }
        }

        // ---- online softmax per m-half ----
        float mn[2][2], fs[2][2];
        bool upd = false;
#pragma unroll
        for (int mh = 0; mh < 2; mh++) {
            float mx0 = -1e30f, mx1 = -1e30f;
#pragma unroll
            for (int nt = 0; nt < 8; nt++) {
                mx0 = fmaxf(mx0, fmaxf(sacc[mh][nt][0], sacc[mh][nt][1]));
                mx1 = fmaxf(mx1, fmaxf(sacc[mh][nt][2], sacc[mh][nt][3]));
            }
            mx0 = fmaxf(mx0, __shfl_xor_sync(0xffffffff, mx0, 1));
            mx0 = fmaxf(mx0, __shfl_xor_sync(0xffffffff, mx0, 2));
            mx1 = fmaxf(mx1, __shfl_xor_sync(0xffffffff, mx1, 1));
            mx1 = fmaxf(mx1, __shfl_xor_sync(0xffffffff, mx1, 2));
            mn[mh][0] = fmaxf(mrun[mh][0], mx0);
            mn[mh][1] = fmaxf(mrun[mh][1], mx1);
            upd |= (mn[mh][0] > mrun[mh][0]) || (mn[mh][1] > mrun[mh][1]);
        }
        if (__any_sync(0xffffffffu, upd)) {
#pragma unroll
            for (int mh = 0; mh < 2; mh++) {
                fs[mh][0] = ex2(mrun[mh][0] - mn[mh][0]);
                fs[mh][1] = ex2(mrun[mh][1] - mn[mh][1]);
                mrun[mh][0] = mn[mh][0]; mrun[mh][1] = mn[mh][1];
#pragma unroll
                for (int nt = 0; nt < 8; nt++) {
                    O[mh][nt][0] *= fs[mh][0]; O[mh][nt][1] *= fs[mh][0];
                    O[mh][nt][2] *= fs[mh][1]; O[mh][nt][3] *= fs[mh][1];
                }
                Oex[mh][0] *= fs[mh][0]; Oex[mh][1] *= fs[mh][0];
                Oex[mh][2] *= fs[mh][1]; Oex[mh][3] *= fs[mh][1];
            }
        }

        uint32_t pa[2][4][4];
#pragma unroll
        for (int mh = 0; mh < 2; mh++)
#pragma unroll
            for (int nt = 0; nt < 8; nt++) {
                uint32_t dlo = pack_bf16(sacc[mh][nt][0] - mn[mh][0],
                                         sacc[mh][nt][1] - mn[mh][0]);
                uint32_t dhi = pack_bf16(sacc[mh][nt][2] - mn[mh][1],
                                         sacc[mh][nt][3] - mn[mh][1]);
                uint32_t p01 = ex2b2(dlo);
                uint32_t p23 = ex2b2(dhi);
                int kt = nt >> 1;
                if ((nt & 1) == 0) { pa[mh][kt][0] = p01; pa[mh][kt][1] = p23; }
                else               { pa[mh][kt][2] = p01; pa[mh][kt][3] = p23; }
            }

        // ---- O += P V, both m-halves share each V fragment ----
        const uint32_t vb = vbase + bo;
        const uint32_t vo = vobase + bo;
#pragma unroll
        for (int ntp = 0; ntp < 4; ntp++) {
#pragma unroll
            for (int kt = 0; kt < 4; kt++) {
                uint32_t r0, r1, r2, r3;
                ldsm_x4t(r0, r1, r2, r3, vb + (kt * 16 * AKS + ntp * 16) * 2);
                uint32_t blo[2] = {r0, r1}, bhi[2] = {r2, r3};
#pragma unroll
                for (int mh = 0; mh < 2; mh++) {
                    mma_bf16(O[mh][2 * ntp], pa[mh][kt], blo);
                    mma_bf16(O[mh][2 * ntp + 1], pa[mh][kt], bhi);
                }
            }
        }
#pragma unroll
        for (int kt = 0; kt < 4; kt++) {
            uint32_t r0, r1;
            ldsm_x2t(r0, r1, vo + (kt * 16 * AKS) * 2);
            uint32_t bx[2] = {r0, r1};
#pragma unroll
            for (int mh = 0; mh < 2; mh++)
                mma_bf16(Oex[mh], pa[mh][kt], bx);
        }
    }

    // ---- epilogue: row sums from quad leader, normalize, store ----
    const int qlead = lane & ~3;
#pragma unroll
    for (int mh = 0; mh < 2; mh++) {
        float l0 = __shfl_sync(0xffffffff, Oex[mh][0], qlead);
        float l1 = __shfl_sync(0xffffffff, Oex[mh][2], qlead);
        float il0 = 1.f / l0, il1 = 1.f / l1;
        const int gr0 = q0 + wrow + mh * 16 + g, gr1 = gr0 + 8;
#pragma unroll
        for (int nt = 0; nt < 8; nt++) {
            int col = nt * 8 + 2 * t;
            float2 o0 = {O[mh][nt][0] * il0, O[mh][nt][1] * il0};
            float2 o1 = {O[mh][nt][2] * il1, O[mh][nt][3] * il1};
            *reinterpret_cast<float2*>(out + (size_t)gr0 * ROWSTR + hoff + col) = o0;
            *reinterpret_cast<float2*>(out + (size_t)gr1 * ROWSTR + hoff + col) = o1;
        }
    }
}

// =================================================================
extern "C" void kernel_launch(void* const* d_in, const int* in_sizes, int n_in,
                              void* d_out, int out_size)
{
    const float* q  = (const float*)d_in[0];
    const float* k  = (const float*)d_in[1];
    const float* v  = (const float*)d_in[2];
    const float* Wq = (const float*)d_in[3];
    const float* bq = (const float*)d_in[4];
    const float* Wk = (const float*)d_in[5];
    const float* bk = (const float*)d_in[6];
    const float* Wv = (const float*)d_in[7];
    const float* bv = (const float*)d_in[8];
    float* out = (float*)d_out;

    __nv_bfloat16 *qh, *kh, *vh, *xq, *xk, *xv, *wq, *wk, *wv;
    cudaGetSymbolAddress((void**)&qh, g_qh);
    cudaGetSymbolAddress((void**)&kh, g_kh);
    cudaGetSymbolAddress((void**)&vh, g_vh);
    cudaGetSymbolAddress((void**)&xq, g_xq);
    cudaGetSymbolAddress((void**)&xk, g_xk);
    cudaGetSymbolAddress((void**)&xv, g_xv);
    cudaGetSymbolAddress((void**)&wq, g_wq);
    cudaGetSymbolAddress((void**)&wk, g_wk);
    cudaGetSymbolAddress((void**)&wv, g_wv);

    const int n4i = MR * HID / 4;
    const int n4w = HID * HID / 4;
    cvt3_kernel<<<dim3(n4i / 256, 3), 256>>>(q, k, v, xq, xk, xv, n4i);
    cvt3_kernel<<<dim3(n4w / 256, 3), 256>>>(Wq, Wk, Wv, wq, wk, wv, n4w);

    cudaFuncSetAttribute(proj_kernel,
                         cudaFuncAttributeMaxDynamicSharedMemorySize, PJ_SMEM);
    dim3 pg(HID / 128, MR / 128, 3);
    proj_kernel<<<pg, 256, PJ_SMEM>>>(
        xq, wq, bq, qh,
        xk, wk, bk, kh,
        xv, wv, bv, vh,
        0.125f * LOG2E);

    cudaFuncSetAttribute(attn_kernel,
                         cudaFuncAttributeMaxDynamicSharedMemorySize, ATT_SMEM);
    dim3 ag(TT / 128, NH, BB);
    attn_kernel<<<ag, ATH, ATT_SMEM>>>(qh, kh, vh, out);
}